// round 9
// baseline (speedup 1.0000x reference)
#include <cuda_runtime.h>
#include <math.h>

#define B_  32
#define T_  1024
#define D_  256
#define U_  512
#define G3  1536          // 3*U
#define NCTA_SCAN 128

typedef unsigned long long ull;

// packed fp32x2 FMA: d = a*b + d (elementwise on the two fp32 halves)
#define FMA2(d_, a_, b_) \
    asm("fma.rn.f32x2 %0, %1, %2, %3;" : "=l"(d_) : "l"(a_), "l"(b_), "l"(d_))
// splat a scalar float into both halves of a 64-bit packed reg
#define SPLAT2(d_, s_) \
    asm("mov.b64 %0, {%1, %1};" : "=l"(d_) : "r"(__float_as_uint(s_)))

// fast sigmoid: 1/(1+2^(-x*log2e)) via MUFU.EX2 + MUFU.RCP (~1e-7 rel err)
__device__ __forceinline__ float fsig(float x) {
    float e, r;
    asm("ex2.approx.f32 %0, %1;" : "=f"(e) : "f"(x * -1.442695041f));
    asm("rcp.approx.f32 %0, %1;" : "=f"(r) : "f"(1.0f + e));
    return r;
}
// fast tanh: 2*sigmoid(2x)-1 (~2e-7 rel err)
__device__ __forceinline__ float ftanh(float x) {
    float e, r;
    asm("ex2.approx.f32 %0, %1;" : "=f"(e) : "f"(x * -2.885390082f));
    asm("rcp.approx.f32 %0, %1;" : "=f"(r) : "f"(1.0f + e));
    return fmaf(2.0f, r, -1.0f);
}

// ---------------- scratch (device globals: allocation-free contract) ----------
__device__ float g_xw[(size_t)T_ * B_ * G3];     // [T,B,3U] gate pre-activations
__device__ float g_out0[(size_t)T_ * B_ * U_];   // layer-0 outputs [T,B,U]
__device__ float g_pred0[(size_t)T_ * B_ * U_];  // layer-1 outputs
__device__ float g_pred1[(size_t)T_ * B_ * U_];  // layer-2 outputs
__device__ float g_h[2][B_ * U_];                // double-buffered hidden state
__device__ unsigned g_flags[NCTA_SCAN];          // per-CTA arrival flags
__device__ volatile unsigned g_bar_gen = 0;      // release word

// ---------------- grid barrier: parallel flag arrive + 1-warp aggregator ------
// Arrive: tid0 fence + relaxed-store to OWN flag (distinct addrs: no LTS
// serialization — replaces the ~3500-cyc same-address atomicAdd chain).
// Aggregate: CTA0 warp0 strong-polls all 128 flags (32 lanes x 4), ballots,
// then fence + relaxed-store of the generation word.
// Wait: round-7-proven single volatile spinner per CTA.
__device__ __forceinline__ void grid_barrier(unsigned target) {
    __syncthreads();                              // all CTA work issued
    if (threadIdx.x == 0) {
        __threadfence();                          // release h-stores
        asm volatile("st.relaxed.gpu.global.u32 [%0], %1;"
                     :: "l"(&g_flags[blockIdx.x]), "r"(target) : "memory");
    }
    if (blockIdx.x == 0) {
        if (threadIdx.x < 32) {                   // aggregator warp
            const unsigned* fp = &g_flags[threadIdx.x * 4];
            bool done;
            do {
                unsigned v0, v1, v2, v3;
                asm volatile("ld.relaxed.gpu.global.u32 %0, [%1];"
                             : "=r"(v0) : "l"(fp + 0) : "memory");
                asm volatile("ld.relaxed.gpu.global.u32 %0, [%1];"
                             : "=r"(v1) : "l"(fp + 1) : "memory");
                asm volatile("ld.relaxed.gpu.global.u32 %0, [%1];"
                             : "=r"(v2) : "l"(fp + 2) : "memory");
                asm volatile("ld.relaxed.gpu.global.u32 %0, [%1];"
                             : "=r"(v3) : "l"(fp + 3) : "memory");
                done = (v0 >= target) && (v1 >= target) &&
                       (v2 >= target) && (v3 >= target);
            } while (!__all_sync(0xffffffffu, done));
            if (threadIdx.x == 0) {
                __threadfence();                  // order after flag observations
                g_bar_gen = target;               // release all spinners
            }
        }
    } else if (threadIdx.x == 0) {
        while (g_bar_gen < target) { }            // volatile spin, 1 thread/CTA
        __threadfence();                          // acquire
    }
    __syncthreads();                              // broadcast to whole CTA
}

// ---------------- persistent GRU scan (structure identical to round 7/8) ------
__global__ void __launch_bounds__(256, 1) scan_kernel(
    const float* __restrict__ R,
    const float* __restrict__ brec,
    const float* __restrict__ h0vec,
    const float* __restrict__ xw,
    float* __restrict__ out,
    float* __restrict__ hbuf0,
    float* __restrict__ hbuf1)
{
    __shared__ float ws[12 * U_];     // [c][k] col-major: 24 KB

    const int tid = threadIdx.x;
    const int u0  = blockIdx.x * 4;

    for (int idx = tid; idx < U_ * 12; idx += 256) {
        int k = idx / 12, c = idx - k * 12;
        int g = c >> 2, j = c & 3;
        ws[c * U_ + k] = R[(size_t)k * G3 + g * U_ + u0 + j];
    }

    if (tid < 128) {
        int i = blockIdx.x * 128 + tid;
        hbuf0[i] = h0vec[i & (U_ - 1)];
    }

    const int w  = tid >> 5, l = tid & 31;
    const int b0 = w * 4;
    const int lb = l >> 2, uj = l & 3;
    const int gb = b0 + lb;
    const int gu = u0 + uj;
    const bool act = (l < 16);
    const unsigned bit0 = l & 1, bit1 = (l >> 1) & 1;
    const unsigned bit2 = (l >> 2) & 1, bit3 = (l >> 3) & 1;

    float bz = 0.f, brr = 0.f, bh = 0.f;
    if (act) {
        bz  = brec[gu];
        brr = brec[U_ + gu];
        bh  = brec[2 * U_ + gu];
    }

    float xz = 0.f, xr = 0.f, xh = 0.f;
    if (act) {
        const float* xwt = xw + (size_t)gb * G3;
        xz = __ldg(xwt + gu);
        xr = __ldg(xwt + U_ + gu);
        xh = __ldg(xwt + 2 * U_ + gu);
    }

    grid_barrier(1u);

    for (int t = 0; t < T_; t++) {
        const float* hR = (t & 1) ? hbuf1 : hbuf0;
        float*       hW = (t & 1) ? hbuf0 : hbuf1;

        float hold = act ? __ldcg(hR + gb * U_ + gu) : 0.f;

        ull acc[4][12];
        #pragma unroll
        for (int b = 0; b < 4; b++)
            #pragma unroll
            for (int c = 0; c < 12; c++) acc[b][c] = 0ull;

        #pragma unroll
        for (int i2 = 0; i2 < 4; i2++) {
            const int ko = 4 * l + 128 * i2;
            ulonglong2 hq[4];
            #pragma unroll
            for (int b = 0; b < 4; b++)
                hq[b] = __ldcg((const ulonglong2*)(hR + (b0 + b) * U_ + ko));
            #pragma unroll
            for (int c = 0; c < 12; c++) {
                ulonglong2 wq = *(const ulonglong2*)(ws + c * U_ + ko);
                #pragma unroll
                for (int b = 0; b < 4; b++) {
                    FMA2(acc[b][c], hq[b].x, wq.x);
                    FMA2(acc[b][c], hq[b].y, wq.y);
                }
            }
        }

        float A[4][12];
        #pragma unroll
        for (int b = 0; b < 4; b++)
            #pragma unroll
            for (int c = 0; c < 12; c++) {
                float2 v = *reinterpret_cast<float2*>(&acc[b][c]);
                A[b][c] = v.x + v.y;
            }

        // compacted butterfly (verified round 4/7/8)
        #pragma unroll
        for (int b = 0; b < 4; b++)
            #pragma unroll
            for (int c = 0; c < 12; c++)
                A[b][c] += __shfl_xor_sync(0xffffffffu, A[b][c], 16);
        float B8[2][12];
        #pragma unroll
        for (int bl = 0; bl < 2; bl++)
            #pragma unroll
            for (int c = 0; c < 12; c++) {
                float keep = bit3 ? A[2 + bl][c] : A[bl][c];
                float send = bit3 ? A[bl][c]     : A[2 + bl][c];
                B8[bl][c] = keep + __shfl_xor_sync(0xffffffffu, send, 8);
            }
        float B4[12];
        #pragma unroll
        for (int c = 0; c < 12; c++) {
            float keep = bit2 ? B8[1][c] : B8[0][c];
            float send = bit2 ? B8[0][c] : B8[1][c];
            B4[c] = keep + __shfl_xor_sync(0xffffffffu, send, 4);
        }
        float B2[3][2];
        #pragma unroll
        for (int g = 0; g < 3; g++)
            #pragma unroll
            for (int j = 0; j < 2; j++) {
                float keep = bit1 ? B4[g * 4 + 2 + j] : B4[g * 4 + j];
                float send = bit1 ? B4[g * 4 + j]     : B4[g * 4 + 2 + j];
                B2[g][j] = keep + __shfl_xor_sync(0xffffffffu, send, 2);
            }
        float S[3];
        #pragma unroll
        for (int g = 0; g < 3; g++) {
            float keep = bit0 ? B2[g][1] : B2[g][0];
            float send = bit0 ? B2[g][0] : B2[g][1];
            S[g] = keep + __shfl_xor_sync(0xffffffffu, send, 1);
        }

        if (act) {
            float z  = fsig(xz + S[0] + bz);
            float r  = fsig(xr + S[1] + brr);
            float hh = ftanh(xh + r * (S[2] + bh));
            float hnew = z * hold + (1.f - z) * hh;
            __stcg(hW + gb * U_ + gu, hnew + 0.1f * (hold - hnew));  // zoneout
            out[((size_t)t * B_ + gb) * U_ + gu] = hnew;
        }

        if (act && t + 1 < T_) {
            const float* xwt = xw + ((size_t)(t + 1) * B_ + gb) * G3;
            xz = __ldg(xwt + gu);
            xr = __ldg(xwt + U_ + gu);
            xh = __ldg(xwt + 2 * U_ + gu);
        }
        if (t + 1 < T_) grid_barrier((unsigned)(t + 2));
    }
}

// ---------------- fp32 GEMM: 128x64 tile, 8x4 microtile, reg-staged prefetch --
// C = rowmap(A0 + s1*A1 + s2*A2) @ W + bias. Block (0,0) zeroes barrier state.
__global__ void __launch_bounds__(256) gemm_kernel(
    const float* __restrict__ A0, const float* __restrict__ A1,
    const float* __restrict__ A2, const float* __restrict__ avec,
    int ia1, int ia2,
    const float* __restrict__ W, const float* __restrict__ bias,
    float* __restrict__ C, int M, int N, int K, int permA, int permC)
{
    __shared__ float As[16][132];   // [k][m], +4 pad
    __shared__ float Bs[16][64];

    const int tid = threadIdx.x;
    if (blockIdx.x == 0 && blockIdx.y == 0) {
        if (tid < NCTA_SCAN) g_flags[tid] = 0;
        if (tid == 0) g_bar_gen = 0;
    }

    const int bm = blockIdx.x * 128;
    const int bn = blockIdx.y * 64;

    const int ra0 = tid >> 2;            // 0..63
    const int ra1 = ra0 + 64;            // 64..127
    const int ka  = (tid & 3) << 2;      // k offset 0/4/8/12
    const int rb = tid >> 4, cb = (tid & 15) << 2;

    const float s1 = A1 ? avec[ia1] : 0.f;
    const float s2 = A2 ? avec[ia2] : 0.f;

    const int m0 = bm + ra0, m1 = bm + ra1;
    const size_t arow0 = permA ? ((size_t)(m0 & 31) * T_ + (m0 >> 5)) : (size_t)m0;
    const size_t arow1 = permA ? ((size_t)(m1 & 31) * T_ + (m1 >> 5)) : (size_t)m1;
    const float* Ap0a = A0 + arow0 * K + ka;
    const float* Ap0b = A0 + arow1 * K + ka;
    const float* Ap1a = A1 ? (A1 + arow0 * K + ka) : (const float*)0;
    const float* Ap1b = A1 ? (A1 + arow1 * K + ka) : (const float*)0;
    const float* Ap2a = A2 ? (A2 + arow0 * K + ka) : (const float*)0;
    const float* Ap2b = A2 ? (A2 + arow1 * K + ka) : (const float*)0;
    const float* Wp   = W + (size_t)rb * N + bn + cb;

    const int tm = (tid >> 4) << 3;
    const int tn = (tid & 15) << 2;

    ull acc2[8][2];
    #pragma unroll
    for (int i = 0; i < 8; i++) { acc2[i][0] = 0ull; acc2[i][1] = 0ull; }

    float4 av0 = *(const float4*)(Ap0a);
    float4 av1 = *(const float4*)(Ap0b);
    if (A1) {
        float4 t0 = *(const float4*)(Ap1a), t1 = *(const float4*)(Ap1b);
        av0.x += s1 * t0.x; av0.y += s1 * t0.y; av0.z += s1 * t0.z; av0.w += s1 * t0.w;
        av1.x += s1 * t1.x; av1.y += s1 * t1.y; av1.z += s1 * t1.z; av1.w += s1 * t1.w;
    }
    if (A2) {
        float4 t0 = *(const float4*)(Ap2a), t1 = *(const float4*)(Ap2b);
        av0.x += s2 * t0.x; av0.y += s2 * t0.y; av0.z += s2 * t0.z; av0.w += s2 * t0.w;
        av1.x += s2 * t1.x; av1.y += s2 * t1.y; av1.z += s2 * t1.z; av1.w += s2 * t1.w;
    }
    float4 bv = *(const float4*)(Wp);

    for (int k0 = 0; ; k0 += 16) {
        As[ka + 0][ra0] = av0.x; As[ka + 1][ra0] = av0.y;
        As[ka + 2][ra0] = av0.z; As[ka + 3][ra0] = av0.w;
        As[ka + 0][ra1] = av1.x; As[ka + 1][ra1] = av1.y;
        As[ka + 2][ra1] = av1.z; As[ka + 3][ra1] = av1.w;
        *(float4*)&Bs[rb][cb] = bv;
        __syncthreads();

        const bool last = (k0 + 16 >= K);
        if (!last) {
            const int kn = k0 + 16;
            av0 = *(const float4*)(Ap0a + kn);
            av1 = *(const float4*)(Ap0b + kn);
            if (A1) {
                float4 t0 = *(const float4*)(Ap1a + kn), t1 = *(const float4*)(Ap1b + kn);
                av0.x += s1 * t0.x; av0.y += s1 * t0.y; av0.z += s1 * t0.z; av0.w += s1 * t0.w;
                av1.x += s1 * t1.x; av1.y += s1 * t1.y; av1.z += s1 * t1.z; av1.w += s1 * t1.w;
            }
            if (A2) {
                float4 t0 = *(const float4*)(Ap2a + kn), t1 = *(const float4*)(Ap2b + kn);
                av0.x += s2 * t0.x; av0.y += s2 * t0.y; av0.z += s2 * t0.z; av0.w += s2 * t0.w;
                av1.x += s2 * t1.x; av1.y += s2 * t1.y; av1.z += s2 * t1.z; av1.w += s2 * t1.w;
            }
            bv = *(const float4*)(Wp + (size_t)kn * N);
        }

        #pragma unroll
        for (int kk = 0; kk < 16; kk++) {
            float4 aA = *(const float4*)&As[kk][tm];
            float4 aB = *(const float4*)&As[kk][tm + 4];
            ulonglong2 b2 = *(const ulonglong2*)&Bs[kk][tn];
            ull s_[8];
            SPLAT2(s_[0], aA.x); SPLAT2(s_[1], aA.y);
            SPLAT2(s_[2], aA.z); SPLAT2(s_[3], aA.w);
            SPLAT2(s_[4], aB.x); SPLAT2(s_[5], aB.y);
            SPLAT2(s_[6], aB.z); SPLAT2(s_[7], aB.w);
            #pragma unroll
            for (int i = 0; i < 8; i++) {
                FMA2(acc2[i][0], s_[i], b2.x);
                FMA2(acc2[i][1], s_[i], b2.y);
            }
        }
        __syncthreads();
        if (last) break;
    }

    #pragma unroll
    for (int i = 0; i < 8; i++) {
        int m = bm + tm + i;
        size_t crow = permC ? ((size_t)(m & 31) * T_ + (m >> 5)) : (size_t)m;
        float* cp = C + crow * N + bn + tn;
        #pragma unroll
        for (int jp = 0; jp < 2; jp++) {
            float2 v = *reinterpret_cast<float2*>(&acc2[i][jp]);
            cp[2 * jp + 0] = v.x + bias[bn + tn + 2 * jp + 0];
            cp[2 * jp + 1] = v.y + bias[bn + tn + 2 * jp + 1];
        }
    }
}

// ---------------- host orchestration -----------------------------------------
extern "C" void kernel_launch(void* const* d_in, const int* in_sizes, int n_in,
                              void* d_out, int out_size)
{
    const float* x   = (const float*)d_in[0];
    const float* k0  = (const float*)d_in[1];
    const float* r0  = (const float*)d_in[2];
    const float* b0  = (const float*)d_in[3];
    const float* ks  = (const float*)d_in[4];
    const float* rs  = (const float*)d_in[5];
    const float* bs  = (const float*)d_in[6];
    const float* h00 = (const float*)d_in[7];
    const float* h01 = (const float*)d_in[8];
    const float* h02 = (const float*)d_in[9];
    const float* a   = (const float*)d_in[10];
    const float* wd  = (const float*)d_in[11];
    const float* bd  = (const float*)d_in[12];

    float *xw, *out0, *p0, *p1, *hbase;
    cudaGetSymbolAddress((void**)&xw,    g_xw);
    cudaGetSymbolAddress((void**)&out0,  g_out0);
    cudaGetSymbolAddress((void**)&p0,    g_pred0);
    cudaGetSymbolAddress((void**)&p1,    g_pred1);
    cudaGetSymbolAddress((void**)&hbase, g_h);
    float* h0 = hbase;
    float* h1 = hbase + B_ * U_;

    const int M = B_ * T_;
    dim3 gridW(M / 128, G3 / 64);   // 256 x 24
    dim3 gridF(M / 128, D_ / 64);   // 256 x 4

    // ---- layer 0: xw = x @ k0 + b_in ----
    gemm_kernel<<<gridW, 256>>>(x, 0, 0, a, 0, 0, k0, b0, xw, M, G3, D_, 1, 0);
    scan_kernel<<<NCTA_SCAN, 256>>>(r0, b0 + G3, h00, xw, out0, h0, h1);

    // ---- layer 1: input = out0 ----
    gemm_kernel<<<gridW, 256>>>(out0, 0, 0, a, 0, 0, ks, bs, xw, M, G3, U_, 0, 0);
    scan_kernel<<<NCTA_SCAN, 256>>>(rs, bs + G3, h01, xw, p0, h0, h1);

    // ---- layer 2: input = out0 + a[0]*pred0 ----
    gemm_kernel<<<gridW, 256>>>(out0, p0, 0, a, 0, 0, ks, bs, xw, M, G3, U_, 0, 0);
    scan_kernel<<<NCTA_SCAN, 256>>>(rs, bs + G3, h02, xw, p1, h0, h1);

    // ---- final: (out0 + a[1]*pred0 + a[2]*pred1) @ wd + bd -> [B,T,D] ----
    gemm_kernel<<<gridF, 256>>>(out0, p0, p1, a, 1, 2, wd, bd,
                                (float*)d_out, M, D_, U_, 0, 1);
}

// round 10
// speedup vs baseline: 1.0942x; 1.0942x over previous
#include <cuda_runtime.h>
#include <math.h>

#define B_  32
#define T_  1024
#define D_  256
#define U_  512
#define G3  1536          // 3*U
#define NCTA_SCAN 128
#define NGRP 4            // independent batch groups
#define GCTA 32           // CTAs per group
#define GB   8            // batches per group
#define WS_BYTES (48 * U_ * 4)   // 96 KB weights per CTA (dynamic SMEM)

typedef unsigned long long ull;

// packed fp32x2 FMA: d = a*b + d (elementwise on the two fp32 halves)
#define FMA2(d_, a_, b_) \
    asm("fma.rn.f32x2 %0, %1, %2, %3;" : "=l"(d_) : "l"(a_), "l"(b_), "l"(d_))
// splat a scalar float into both halves of a 64-bit packed reg
#define SPLAT2(d_, s_) \
    asm("mov.b64 %0, {%1, %1};" : "=l"(d_) : "r"(__float_as_uint(s_)))

// fast sigmoid / tanh via MUFU.EX2 + MUFU.RCP (~1-2e-7 rel err)
__device__ __forceinline__ float fsig(float x) {
    float e, r;
    asm("ex2.approx.f32 %0, %1;" : "=f"(e) : "f"(x * -1.442695041f));
    asm("rcp.approx.f32 %0, %1;" : "=f"(r) : "f"(1.0f + e));
    return r;
}
__device__ __forceinline__ float ftanh(float x) {
    float e, r;
    asm("ex2.approx.f32 %0, %1;" : "=f"(e) : "f"(x * -2.885390082f));
    asm("rcp.approx.f32 %0, %1;" : "=f"(r) : "f"(1.0f + e));
    return fmaf(2.0f, r, -1.0f);
}

// ---------------- scratch (device globals: allocation-free contract) ----------
__device__ float g_xw[(size_t)T_ * B_ * G3];     // [T,B,3U] gate pre-activations
__device__ float g_out0[(size_t)T_ * B_ * U_];   // layer-0 outputs [T,B,U]
__device__ float g_pred0[(size_t)T_ * B_ * U_];  // layer-1 outputs
__device__ float g_pred1[(size_t)T_ * B_ * U_];  // layer-2 outputs
__device__ float g_h[2][B_ * U_];                // double-buffered hidden state
__device__ unsigned g_bar_count[NGRP * 32];      // per-group, 128B apart
__device__ volatile unsigned g_bar_gen[NGRP * 32];

// ---------------- per-group barrier: atomic arrive + single volatile spinner --
// Round-8-proven mechanism, scoped to 32 CTAs (one batch group).
__device__ __forceinline__ void group_barrier(int grp, unsigned target) {
    __syncthreads();
    if (threadIdx.x == 0) {
        __threadfence();                           // release h-stores
        unsigned arrived = atomicAdd(&g_bar_count[grp * 32], 1u);
        if (arrived == GCTA - 1u) {
            g_bar_count[grp * 32] = 0;
            __threadfence();
            g_bar_gen[grp * 32] = target;          // release group's spinners
        } else {
            while (g_bar_gen[grp * 32] < target) { }
        }
        __threadfence();                           // acquire
    }
    __syncthreads();
}

// ---------------- persistent GRU scan: 4 groups x 32 CTAs --------------------
// Group g owns batches 8g..8g+7; CTA-in-group owns 16 units (48 gate cols,
// 96 KB weights in dynamic SMEM). Warp = (batch-quad, col-quarter): 4 batches
// x 12 cols — identical inner-loop shape to round 8.
__global__ void __launch_bounds__(256, 1) scan_kernel(
    const float* __restrict__ R,
    const float* __restrict__ brec,
    const float* __restrict__ h0vec,
    const float* __restrict__ xw,
    float* __restrict__ out,
    float* __restrict__ hbuf0,
    float* __restrict__ hbuf1)
{
    extern __shared__ float ws[];     // [cq][c12][k]: 4*12*512 floats = 96 KB

    const int tid = threadIdx.x;
    const int grp = blockIdx.x >> 5;          // 0..3
    const int cig = blockIdx.x & 31;          // CTA within group
    const int u0g = cig * 16;                 // first global unit owned

    // Preload 48 recurrent columns: ws[cq*6144 + c12*512 + k]
    // c12 = g*4 + j  -> global unit = u0g + cq*4 + j, gate g
    for (int idx = tid; idx < 48 * U_; idx += 256) {
        int k = idx / 48, c = idx - k * 48;
        int cq = c / 12, c12 = c - cq * 12;
        int g = c12 >> 2, j = c12 & 3;
        ws[cq * (12 * U_) + c12 * U_ + k] =
            R[(size_t)k * G3 + g * U_ + (u0g + cq * 4 + j)];
    }

    // h init: CTA writes its (8 batches x 16 units) slice of hbuf0.
    if (tid < 128) {
        int bl = tid >> 4, ul = tid & 15;
        int u = u0g + ul;
        hbuf0[(grp * GB + bl) * U_ + u] = h0vec[u];
    }

    const int w  = tid >> 5, l = tid & 31;
    const int q  = w >> 2;                    // batch quad (0..1)
    const int cq = w & 3;                     // col quarter (0..3)
    const int b0 = grp * GB + q * 4;          // first batch of this warp
    const float* wsq = ws + cq * (12 * U_);

    const int lb = l >> 2, uj = l & 3;
    const int gb = b0 + lb;                   // batch handled by act-lane
    const int gu = u0g + cq * 4 + uj;         // global unit handled
    const bool act = (l < 16);
    const unsigned bit0 = l & 1, bit1 = (l >> 1) & 1;
    const unsigned bit2 = (l >> 2) & 1, bit3 = (l >> 3) & 1;

    float bz = 0.f, brr = 0.f, bh = 0.f;
    if (act) {
        bz  = brec[gu];
        brr = brec[U_ + gu];
        bh  = brec[2 * U_ + gu];
    }

    float xz = 0.f, xr = 0.f, xh = 0.f;
    if (act) {
        const float* xwt = xw + (size_t)gb * G3;
        xz = __ldg(xwt + gu);
        xr = __ldg(xwt + U_ + gu);
        xh = __ldg(xwt + 2 * U_ + gu);
    }

    group_barrier(grp, 1u);   // ws + h slices visible group-wide

    for (int t = 0; t < T_; t++) {
        const float* hR = (t & 1) ? hbuf1 : hbuf0;
        float*       hW = (t & 1) ? hbuf0 : hbuf1;

        float hold = act ? __ldcg(hR + gb * U_ + gu) : 0.f;

        ull acc[4][12];
        #pragma unroll
        for (int b = 0; b < 4; b++)
            #pragma unroll
            for (int c = 0; c < 12; c++) acc[b][c] = 0ull;

        #pragma unroll
        for (int i2 = 0; i2 < 4; i2++) {
            const int ko = 4 * l + 128 * i2;
            ulonglong2 hq[4];
            #pragma unroll
            for (int b = 0; b < 4; b++)
                hq[b] = __ldcg((const ulonglong2*)(hR + (b0 + b) * U_ + ko));
            #pragma unroll
            for (int c = 0; c < 12; c++) {
                ulonglong2 wq = *(const ulonglong2*)(wsq + c * U_ + ko);
                #pragma unroll
                for (int b = 0; b < 4; b++) {
                    FMA2(acc[b][c], hq[b].x, wq.x);
                    FMA2(acc[b][c], hq[b].y, wq.y);
                }
            }
        }

        float A[4][12];
        #pragma unroll
        for (int b = 0; b < 4; b++)
            #pragma unroll
            for (int c = 0; c < 12; c++) {
                float2 v = *reinterpret_cast<float2*>(&acc[b][c]);
                A[b][c] = v.x + v.y;
            }

        // compacted butterfly (verified rounds 4/7/8/9)
        #pragma unroll
        for (int b = 0; b < 4; b++)
            #pragma unroll
            for (int c = 0; c < 12; c++)
                A[b][c] += __shfl_xor_sync(0xffffffffu, A[b][c], 16);
        float B8[2][12];
        #pragma unroll
        for (int bl = 0; bl < 2; bl++)
            #pragma unroll
            for (int c = 0; c < 12; c++) {
                float keep = bit3 ? A[2 + bl][c] : A[bl][c];
                float send = bit3 ? A[bl][c]     : A[2 + bl][c];
                B8[bl][c] = keep + __shfl_xor_sync(0xffffffffu, send, 8);
            }
        float B4[12];
        #pragma unroll
        for (int c = 0; c < 12; c++) {
            float keep = bit2 ? B8[1][c] : B8[0][c];
            float send = bit2 ? B8[0][c] : B8[1][c];
            B4[c] = keep + __shfl_xor_sync(0xffffffffu, send, 4);
        }
        float B2[3][2];
        #pragma unroll
        for (int g = 0; g < 3; g++)
            #pragma unroll
            for (int j = 0; j < 2; j++) {
                float keep = bit1 ? B4[g * 4 + 2 + j] : B4[g * 4 + j];
                float send = bit1 ? B4[g * 4 + j]     : B4[g * 4 + 2 + j];
                B2[g][j] = keep + __shfl_xor_sync(0xffffffffu, send, 2);
            }
        float S[3];
        #pragma unroll
        for (int g = 0; g < 3; g++) {
            float keep = bit0 ? B2[g][1] : B2[g][0];
            float send = bit0 ? B2[g][0] : B2[g][1];
            S[g] = keep + __shfl_xor_sync(0xffffffffu, send, 1);
        }

        if (act) {
            float z  = fsig(xz + S[0] + bz);
            float r  = fsig(xr + S[1] + brr);
            float hh = ftanh(xh + r * (S[2] + bh));
            float hnew = z * hold + (1.f - z) * hh;
            __stcg(hW + gb * U_ + gu, hnew + 0.1f * (hold - hnew));  // zoneout
            out[((size_t)t * B_ + gb) * U_ + gu] = hnew;
        }

        if (act && t + 1 < T_) {
            const float* xwt = xw + ((size_t)(t + 1) * B_ + gb) * G3;
            xz = __ldg(xwt + gu);
            xr = __ldg(xwt + U_ + gu);
            xh = __ldg(xwt + 2 * U_ + gu);
        }
        if (t + 1 < T_) group_barrier(grp, (unsigned)(t + 2));
    }
}

// ---------------- fp32 GEMM: 128x64 tile, 8x4 microtile, reg-staged prefetch --
// C = rowmap(A0 + s1*A1 + s2*A2) @ W + bias. Block (0,0) zeroes barrier state.
__global__ void __launch_bounds__(256) gemm_kernel(
    const float* __restrict__ A0, const float* __restrict__ A1,
    const float* __restrict__ A2, const float* __restrict__ avec,
    int ia1, int ia2,
    const float* __restrict__ W, const float* __restrict__ bias,
    float* __restrict__ C, int M, int N, int K, int permA, int permC)
{
    __shared__ float As[16][132];   // [k][m], +4 pad
    __shared__ float Bs[16][64];

    const int tid = threadIdx.x;
    if (blockIdx.x == 0 && blockIdx.y == 0 && tid < NGRP) {
        g_bar_count[tid * 32] = 0;
        g_bar_gen[tid * 32]   = 0;
    }

    const int bm = blockIdx.x * 128;
    const int bn = blockIdx.y * 64;

    const int ra0 = tid >> 2;            // 0..63
    const int ra1 = ra0 + 64;            // 64..127
    const int ka  = (tid & 3) << 2;      // k offset 0/4/8/12
    const int rb = tid >> 4, cb = (tid & 15) << 2;

    const float s1 = A1 ? avec[ia1] : 0.f;
    const float s2 = A2 ? avec[ia2] : 0.f;

    const int m0 = bm + ra0, m1 = bm + ra1;
    const size_t arow0 = permA ? ((size_t)(m0 & 31) * T_ + (m0 >> 5)) : (size_t)m0;
    const size_t arow1 = permA ? ((size_t)(m1 & 31) * T_ + (m1 >> 5)) : (size_t)m1;
    const float* Ap0a = A0 + arow0 * K + ka;
    const float* Ap0b = A0 + arow1 * K + ka;
    const float* Ap1a = A1 ? (A1 + arow0 * K + ka) : (const float*)0;
    const float* Ap1b = A1 ? (A1 + arow1 * K + ka) : (const float*)0;
    const float* Ap2a = A2 ? (A2 + arow0 * K + ka) : (const float*)0;
    const float* Ap2b = A2 ? (A2 + arow1 * K + ka) : (const float*)0;
    const float* Wp   = W + (size_t)rb * N + bn + cb;

    const int tm = (tid >> 4) << 3;
    const int tn = (tid & 15) << 2;

    ull acc2[8][2];
    #pragma unroll
    for (int i = 0; i < 8; i++) { acc2[i][0] = 0ull; acc2[i][1] = 0ull; }

    float4 av0 = *(const float4*)(Ap0a);
    float4 av1 = *(const float4*)(Ap0b);
    if (A1) {
        float4 t0 = *(const float4*)(Ap1a), t1 = *(const float4*)(Ap1b);
        av0.x += s1 * t0.x; av0.y += s1 * t0.y; av0.z += s1 * t0.z; av0.w += s1 * t0.w;
        av1.x += s1 * t1.x; av1.y += s1 * t1.y; av1.z += s1 * t1.z; av1.w += s1 * t1.w;
    }
    if (A2) {
        float4 t0 = *(const float4*)(Ap2a), t1 = *(const float4*)(Ap2b);
        av0.x += s2 * t0.x; av0.y += s2 * t0.y; av0.z += s2 * t0.z; av0.w += s2 * t0.w;
        av1.x += s2 * t1.x; av1.y += s2 * t1.y; av1.z += s2 * t1.z; av1.w += s2 * t1.w;
    }
    float4 bv = *(const float4*)(Wp);

    for (int k0 = 0; ; k0 += 16) {
        As[ka + 0][ra0] = av0.x; As[ka + 1][ra0] = av0.y;
        As[ka + 2][ra0] = av0.z; As[ka + 3][ra0] = av0.w;
        As[ka + 0][ra1] = av1.x; As[ka + 1][ra1] = av1.y;
        As[ka + 2][ra1] = av1.z; As[ka + 3][ra1] = av1.w;
        *(float4*)&Bs[rb][cb] = bv;
        __syncthreads();

        const bool last = (k0 + 16 >= K);
        if (!last) {
            const int kn = k0 + 16;
            av0 = *(const float4*)(Ap0a + kn);
            av1 = *(const float4*)(Ap0b + kn);
            if (A1) {
                float4 t0 = *(const float4*)(Ap1a + kn), t1 = *(const float4*)(Ap1b + kn);
                av0.x += s1 * t0.x; av0.y += s1 * t0.y; av0.z += s1 * t0.z; av0.w += s1 * t0.w;
                av1.x += s1 * t1.x; av1.y += s1 * t1.y; av1.z += s1 * t1.z; av1.w += s1 * t1.w;
            }
            if (A2) {
                float4 t0 = *(const float4*)(Ap2a + kn), t1 = *(const float4*)(Ap2b + kn);
                av0.x += s2 * t0.x; av0.y += s2 * t0.y; av0.z += s2 * t0.z; av0.w += s2 * t0.w;
                av1.x += s2 * t1.x; av1.y += s2 * t1.y; av1.z += s2 * t1.z; av1.w += s2 * t1.w;
            }
            bv = *(const float4*)(Wp + (size_t)kn * N);
        }

        #pragma unroll
        for (int kk = 0; kk < 16; kk++) {
            float4 aA = *(const float4*)&As[kk][tm];
            float4 aB = *(const float4*)&As[kk][tm + 4];
            ulonglong2 b2 = *(const ulonglong2*)&Bs[kk][tn];
            ull s_[8];
            SPLAT2(s_[0], aA.x); SPLAT2(s_[1], aA.y);
            SPLAT2(s_[2], aA.z); SPLAT2(s_[3], aA.w);
            SPLAT2(s_[4], aB.x); SPLAT2(s_[5], aB.y);
            SPLAT2(s_[6], aB.z); SPLAT2(s_[7], aB.w);
            #pragma unroll
            for (int i = 0; i < 8; i++) {
                FMA2(acc2[i][0], s_[i], b2.x);
                FMA2(acc2[i][1], s_[i], b2.y);
            }
        }
        __syncthreads();
        if (last) break;
    }

    #pragma unroll
    for (int i = 0; i < 8; i++) {
        int m = bm + tm + i;
        size_t crow = permC ? ((size_t)(m & 31) * T_ + (m >> 5)) : (size_t)m;
        float* cp = C + crow * N + bn + tn;
        #pragma unroll
        for (int jp = 0; jp < 2; jp++) {
            float2 v = *reinterpret_cast<float2*>(&acc2[i][jp]);
            cp[2 * jp + 0] = v.x + bias[bn + tn + 2 * jp + 0];
            cp[2 * jp + 1] = v.y + bias[bn + tn + 2 * jp + 1];
        }
    }
}

// ---------------- host orchestration -----------------------------------------
extern "C" void kernel_launch(void* const* d_in, const int* in_sizes, int n_in,
                              void* d_out, int out_size)
{
    const float* x   = (const float*)d_in[0];
    const float* k0  = (const float*)d_in[1];
    const float* r0  = (const float*)d_in[2];
    const float* b0  = (const float*)d_in[3];
    const float* ks  = (const float*)d_in[4];
    const float* rs  = (const float*)d_in[5];
    const float* bs  = (const float*)d_in[6];
    const float* h00 = (const float*)d_in[7];
    const float* h01 = (const float*)d_in[8];
    const float* h02 = (const float*)d_in[9];
    const float* a   = (const float*)d_in[10];
    const float* wd  = (const float*)d_in[11];
    const float* bd  = (const float*)d_in[12];

    float *xw, *out0, *p0, *p1, *hbase;
    cudaGetSymbolAddress((void**)&xw,    g_xw);
    cudaGetSymbolAddress((void**)&out0,  g_out0);
    cudaGetSymbolAddress((void**)&p0,    g_pred0);
    cudaGetSymbolAddress((void**)&p1,    g_pred1);
    cudaGetSymbolAddress((void**)&hbase, g_h);
    float* h0 = hbase;
    float* h1 = hbase + B_ * U_;

    // allow 96 KB dynamic SMEM for the scan (idempotent; not a stream op)
    static int smem_set = 0;
    if (!smem_set) {
        cudaFuncSetAttribute(scan_kernel,
                             cudaFuncAttributeMaxDynamicSharedMemorySize, WS_BYTES);
        smem_set = 1;
    }

    const int M = B_ * T_;
    dim3 gridW(M / 128, G3 / 64);   // 256 x 24
    dim3 gridF(M / 128, D_ / 64);   // 256 x 4

    // ---- layer 0: xw = x @ k0 + b_in ----
    gemm_kernel<<<gridW, 256>>>(x, 0, 0, a, 0, 0, k0, b0, xw, M, G3, D_, 1, 0);
    scan_kernel<<<NCTA_SCAN, 256, WS_BYTES>>>(r0, b0 + G3, h00, xw, out0, h0, h1);

    // ---- layer 1: input = out0 ----
    gemm_kernel<<<gridW, 256>>>(out0, 0, 0, a, 0, 0, ks, bs, xw, M, G3, U_, 0, 0);
    scan_kernel<<<NCTA_SCAN, 256, WS_BYTES>>>(rs, bs + G3, h01, xw, p0, h0, h1);

    // ---- layer 2: input = out0 + a[0]*pred0 ----
    gemm_kernel<<<gridW, 256>>>(out0, p0, 0, a, 0, 0, ks, bs, xw, M, G3, U_, 0, 0);
    scan_kernel<<<NCTA_SCAN, 256, WS_BYTES>>>(rs, bs + G3, h02, xw, p1, h0, h1);

    // ---- final: (out0 + a[1]*pred0 + a[2]*pred1) @ wd + bd -> [B,T,D] ----
    gemm_kernel<<<gridF, 256>>>(out0, p0, p1, a, 1, 2, wd, bd,
                                (float*)d_out, M, D_, U_, 0, 1);
}